// round 14
// baseline (speedup 1.0000x reference)
#include <cuda_runtime.h>
#include <cuda_fp16.h>
#include <cstdint>

// ---------------- problem dims ----------------
#define BSZ   2048
#define TST   100
#define EMB   200
#define SDIM  12
#define GDIM  600            // 3*EMB
#define MBIG  (TST*BSZ)      // 204800 rows
#define MROWS ((TST+1)*BSZ)  // 206848 rows
#define EPSV  1e-4f

typedef unsigned long long ull;

__device__ __forceinline__ ull ffma2(ull a, ull b, ull c) {
    ull d;
    asm("fma.rn.f32x2 %0, %1, %2, %3;" : "=l"(d) : "l"(a), "l"(b), "l"(c));
    return d;
}
__device__ __forceinline__ ull pack2(float lo, float hi) {
    ull d;
    asm("mov.b64 %0, {%1, %2};" : "=l"(d) : "f"(lo), "f"(hi));
    return d;
}
__device__ __forceinline__ float2 unpack2(ull v) {
    float2 r;
    asm("mov.b64 {%0, %1}, %2;" : "=f"(r.x), "=f"(r.y) : "l"(v));
    return r;
}
__device__ __forceinline__ uint32_t smem_u32(const void* p) {
    uint32_t a;
    asm("{ .reg .u64 t; cvta.to.shared.u64 t, %1; cvt.u32.u64 %0, t; }" : "=r"(a) : "l"(p));
    return a;
}

// mma.sync m16n8k16 f16 -> f32 accum
__device__ __forceinline__ void mma_f16(float c[4],
                                        uint32_t a0, uint32_t a1, uint32_t a2, uint32_t a3,
                                        uint32_t b0, uint32_t b1) {
    asm volatile(
        "mma.sync.aligned.m16n8k16.row.col.f32.f16.f16.f32 "
        "{%0,%1,%2,%3}, {%4,%5,%6,%7}, {%8,%9}, {%0,%1,%2,%3};"
        : "+f"(c[0]), "+f"(c[1]), "+f"(c[2]), "+f"(c[3])
        : "r"(a0), "r"(a1), "r"(a2), "r"(a3), "r"(b0), "r"(b1));
}

__device__ __forceinline__ void ldsm_x4(uint32_t& r0, uint32_t& r1, uint32_t& r2, uint32_t& r3,
                                        uint32_t addr) {
    asm volatile("ldmatrix.sync.aligned.m8n8.x4.shared.b16 {%0,%1,%2,%3}, [%4];"
                 : "=r"(r0), "=r"(r1), "=r"(r2), "=r"(r3) : "r"(addr));
}

__device__ __forceinline__ void cp16h(uint32_t daddr, const __half* src, uint32_t bytes) {
    asm volatile("cp.async.ca.shared.global [%0], [%1], 16, %2;"
                 :: "r"(daddr), "l"(src), "r"(bytes));
}
#define CP_COMMIT()  asm volatile("cp.async.commit_group;" ::: "memory")
#define CP_WAIT_1()  asm volatile("cp.async.wait_group 1;" ::: "memory")
#define CP_WAIT_0()  asm volatile("cp.async.wait_group 0;" ::: "memory")

// ---------------- device scratch ----------------
__device__ __align__(128) float  g_gibase[BSZ * GDIM];
__device__ __align__(128) float  g_h0[BSZ * EMB];
__device__ __align__(128) float  g_whh_t[EMB * GDIM];
__device__ __align__(128) float  g_bdc[400];                      // packed dec_b1|cov_b1
__device__ __align__(128) __half g_h1h[(size_t)MBIG * EMB];       // ae layer-1 out
__device__ __align__(128) __half g_h1hb[(size_t)MBIG * EMB];      // lce layer-1 out
__device__ __align__(128) __half g_ctxh[BSZ * EMB];
__device__ __align__(128) __half g_alch[(size_t)MBIG * 400];
__device__ __align__(128) __half g_gih[(size_t)MBIG * GDIM];
__device__ __align__(128) __half g_hidh[(size_t)MROWS * EMB];
__device__ __align__(128) __half g_tmph[(size_t)MROWS * 400];     // fused dec|cov hidden (half)
__device__ __align__(128) __half g_uh[(size_t)MBIG * 8];          // padded half u
__device__ __align__(128) __half g_lch[(size_t)MBIG * 8];         // padded half lctx
__device__ __align__(128) __half g_wh[604000];

#define WH_SE   0
#define WH_CE   40000
#define WH_AE   80000
#define WH_LCE  120000
#define WH_DEC  160000      // dec_w1 rows 0-199 ...
#define WH_COV  200000      // ... cov_w1 rows 200-399 (contiguous => [400][200])
#define WH_WIH  240000      // 600x600
#define WH_AE1  600000      // ae_w1 padded [200][8]
#define WH_LCE1 601600      // lce_w1 padded [200][8]

// ---------------- fp16 tensor-core GEMM: 4 warps, warp tile 32x128, ILP-pipelined ----------------
#define ROWB      144                 // bytes per smem tile row (64 halves + 8 pad)
#define TILE_B    (128 * ROWB)        // 18432
#define BUF_B     (2 * TILE_B)        // 36864
#define HM_SMEM   (2 * BUF_B)         // 73728
#define HM_THREADS 128

enum { ACT_NONE = 0, ACT_RELU = 1, ACT_TANH = 2 };

// stage [128 rows x 64 halves] via cp.async (zero-fills beyond K / rows); 128 threads
__device__ __forceinline__ void stage_h64(uint32_t sbase, const __half* __restrict__ src,
                                          int ld, int row0, int rowsValid,
                                          int k0, int K, int tid)
{
#pragma unroll
    for (int pass = 0; pass < 8; pass++) {
        int e = tid + pass * 128;
        int r = e >> 3, c = e & 7;
        int ks = k0 + c * 8;
        int valid = (r < rowsValid) ? min(max((K - ks) * 2, 0), 16) : 0;
        const __half* g = src + (size_t)(row0 + ((r < rowsValid) ? r : 0)) * ld + (valid ? ks : 0);
        cp16h(sbase + (uint32_t)(r * ROWB + c * 16), g, (uint32_t)valid);
    }
}

// shared mainloop+epilogue body (4 warps; warp w owns rows [w*32, w*32+32), all 128 cols)
template <int ACT, bool HAS_BASE>
__device__ __forceinline__ void hm_body(
        const __half* __restrict__ A, int lda,
        const __half* __restrict__ W, int ldw,
        const float* __restrict__ bias,
        const float* __restrict__ base, int baseMask,
        float* __restrict__ outF, int ldf,
        __half* __restrict__ outH, int ldh,
        int M, int N, int K, char* smh)
{
    const uint32_t smem_base = smem_u32(smh);

    const int tid  = threadIdx.x;
    const int wid  = tid >> 5;          // 0..3 -> warp_m
    const int lane = tid & 31;
    const int bm = blockIdx.y * 128;
    const int bn = blockIdx.x * 128;
    const int nValid = min(128, N - bn);

    const int lg = lane >> 2;
    const int lt = lane & 3;

    const uint32_t aRow = (uint32_t)(wid * 32 + (lane & 15));
    const uint32_t aOff = aRow * ROWB + ((lane >> 4) << 3) * 2;
    const uint32_t bRow = (uint32_t)(((lane >> 4) & 1) * 8 + (lane & 7));   // within 16-row group
    const uint32_t bOff = bRow * ROWB + (((lane >> 3) & 1) << 3) * 2;

    float acc[2][16][4];
#pragma unroll
    for (int mt = 0; mt < 2; mt++)
#pragma unroll
        for (int nt = 0; nt < 16; nt++)
#pragma unroll
            for (int j = 0; j < 4; j++) acc[mt][nt][j] = 0.f;

    const int nk = (K + 63) / 64;

    stage_h64(smem_base,          A, lda, bm, 128,    0, K, tid);
    stage_h64(smem_base + TILE_B, W, ldw, bn, nValid, 0, K, tid);
    CP_COMMIT();

    for (int kc = 0; kc < nk; kc++) {
        if (kc + 1 < nk) {
            uint32_t nb = smem_base + (uint32_t)(((kc + 1) & 1) * BUF_B);
            int k0n = (kc + 1) * 64;
            stage_h64(nb,          A, lda, bm, 128,    k0n, K, tid);
            stage_h64(nb + TILE_B, W, ldw, bn, nValid, k0n, K, tid);
            CP_COMMIT();
            CP_WAIT_1();
        } else {
            CP_WAIT_0();
        }
        __syncthreads();

        const uint32_t aBase = smem_base + (uint32_t)((kc & 1) * BUF_B) + aOff;
        const uint32_t bBase = smem_base + (uint32_t)((kc & 1) * BUF_B) + TILE_B + bOff;

        const int kRem = K - kc * 64;
        const int kkmax = min(4, (kRem + 15) >> 4);

#pragma unroll 4
        for (int kk = 0; kk < kkmax; kk++) {
            const uint32_t kByte = (uint32_t)(kk * 32);
            uint32_t af[2][4];
            ldsm_x4(af[0][0], af[0][1], af[0][2], af[0][3], aBase + kByte);
            ldsm_x4(af[1][0], af[1][1], af[1][2], af[1][3], aBase + 16 * ROWB + kByte);

            // prefetched n-walk: ldsm for group nt2+1 issued before MMAs of nt2
            uint32_t bc0, bc1, bc2, bc3;
            ldsm_x4(bc0, bc1, bc2, bc3, bBase + kByte);
#pragma unroll
            for (int nt2 = 0; nt2 < 8; nt2++) {
                uint32_t bn0, bn1, bn2, bn3;
                if (nt2 < 7)
                    ldsm_x4(bn0, bn1, bn2, bn3,
                            bBase + (uint32_t)((nt2 + 1) * 16 * ROWB) + kByte);
                mma_f16(acc[0][2 * nt2],     af[0][0], af[0][1], af[0][2], af[0][3], bc0, bc1);
                mma_f16(acc[1][2 * nt2],     af[1][0], af[1][1], af[1][2], af[1][3], bc0, bc1);
                mma_f16(acc[0][2 * nt2 + 1], af[0][0], af[0][1], af[0][2], af[0][3], bc2, bc3);
                mma_f16(acc[1][2 * nt2 + 1], af[1][0], af[1][1], af[1][2], af[1][3], bc2, bc3);
                if (nt2 < 7) { bc0 = bn0; bc1 = bn1; bc2 = bn2; bc3 = bn3; }
            }
        }
        __syncthreads();
    }

#pragma unroll
    for (int mt = 0; mt < 2; mt++) {
        int gm0 = bm + wid * 32 + mt * 16 + lg;
        const float* base0 = HAS_BASE ? (base + (size_t)(gm0 & baseMask) * GDIM) : nullptr;
        const float* base1 = HAS_BASE ? (base + (size_t)((gm0 + 8) & baseMask) * GDIM) : nullptr;
#pragma unroll
        for (int nt = 0; nt < 16; nt++) {
            int gnl = nt * 8 + lt * 2;
            if (gnl >= nValid) continue;
            int gn = bn + gnl;
            float b0v = bias ? bias[gn]     : 0.f;
            float b1v = bias ? bias[gn + 1] : 0.f;
            float v00 = acc[mt][nt][0] + b0v;
            float v01 = acc[mt][nt][1] + b1v;
            float v10 = acc[mt][nt][2] + b0v;
            float v11 = acc[mt][nt][3] + b1v;
            if (HAS_BASE) {
                v00 += base0[gn]; v01 += base0[gn + 1];
                v10 += base1[gn]; v11 += base1[gn + 1];
            }
            if (ACT == ACT_RELU) {
                v00 = fmaxf(v00, 0.f); v01 = fmaxf(v01, 0.f);
                v10 = fmaxf(v10, 0.f); v11 = fmaxf(v11, 0.f);
            } else if (ACT == ACT_TANH) {
                v00 = tanhf(v00); v01 = tanhf(v01);
                v10 = tanhf(v10); v11 = tanhf(v11);
            }
            if (outF) {
                *reinterpret_cast<float2*>(outF + (size_t)gm0 * ldf + gn)       = make_float2(v00, v01);
                *reinterpret_cast<float2*>(outF + (size_t)(gm0 + 8) * ldf + gn) = make_float2(v10, v11);
            }
            if (outH) {
                *reinterpret_cast<__half2*>(outH + (size_t)gm0 * ldh + gn)       = __floats2half2_rn(v00, v01);
                *reinterpret_cast<__half2*>(outH + (size_t)(gm0 + 8) * ldh + gn) = __floats2half2_rn(v10, v11);
            }
        }
    }
}

template <int ACT, bool HAS_BASE>
__global__ void __launch_bounds__(HM_THREADS, 2)
hm_gemm(const __half* __restrict__ A, int lda,
        const __half* __restrict__ W, int ldw,
        const float* __restrict__ bias,
        const float* __restrict__ base, int baseMask,
        float* __restrict__ outF, int ldf,
        __half* __restrict__ outH, int ldh,
        int M, int N, int K)
{
    extern __shared__ char smh[];
    hm_body<ACT, HAS_BASE>(A, lda, W, ldw, bias, base, baseMask,
                           outF, ldf, outH, ldh, M, N, K, smh);
}

// paired variant: blockIdx.z selects op (same shapes; relu; half out only)
__global__ void __launch_bounds__(HM_THREADS, 2)
hm_gemm_pair(const __half* A0, const __half* W0, const float* b0, __half* o0,
             const __half* A1, const __half* W1, const float* b1, __half* o1,
             int lda, int ldw, int ldh, int M, int N, int K)
{
    extern __shared__ char smh[];
    if (blockIdx.z == 0)
        hm_body<ACT_RELU, false>(A0, lda, W0, ldw, b0, nullptr, 0,
                                 nullptr, 0, o0, ldh, M, N, K, smh);
    else
        hm_body<ACT_RELU, false>(A1, lda, W1, ldw, b1, nullptr, 0,
                                 nullptr, 0, o1, ldh, M, N, K, smh);
}

// ---------------- tiny-K first layer (half output; small M only) ----------------
__global__ void embed1_kernel(const float* __restrict__ X,
                              const float* __restrict__ W,
                              const float* __restrict__ B,
                              __half* __restrict__ Y, int M, int K)
{
    int idx = blockIdx.x * blockDim.x + threadIdx.x;
    if (idx >= M * EMB) return;
    int m = idx / EMB, j = idx - m * EMB;
    const float* xr = X + (size_t)m * K;
    const float* wr = W + (size_t)j * K;
    float s = B[j];
    for (int k = 0; k < K; k++) s = fmaf(xr[k], wr[k], s);
    Y[idx] = __float2half(fmaxf(s, 0.f));
}

// ---------------- convert weights to half (+ padded layer-1 weights, dec|cov bias) ----------------
__global__ void conv_w_kernel(const float* __restrict__ se, const float* __restrict__ ce,
                              const float* __restrict__ ae, const float* __restrict__ lce,
                              const float* __restrict__ dec, const float* __restrict__ cov,
                              const float* __restrict__ wih, __half* __restrict__ wh,
                              const float* __restrict__ decb, const float* __restrict__ covb,
                              float* __restrict__ bdc,
                              const float* __restrict__ aew1, const float* __restrict__ lcew1)
{
    int i = blockIdx.x * blockDim.x + threadIdx.x;
    if (i < 40000) {
        wh[WH_SE  + i] = __float2half(se[i]);
        wh[WH_CE  + i] = __float2half(ce[i]);
        wh[WH_AE  + i] = __float2half(ae[i]);
        wh[WH_LCE + i] = __float2half(lce[i]);
        wh[WH_DEC + i] = __float2half(dec[i]);
        wh[WH_COV + i] = __float2half(cov[i]);
    }
    if (i < 360000) wh[WH_WIH + i] = __float2half(wih[i]);
    if (i < 200) {
        bdc[i]       = decb[i];
        bdc[200 + i] = covb[i];
    }
    if (i < 1600) {
        int r = i >> 3, c = i & 7;
        wh[WH_AE1  + i] = (c < 4) ? __float2half(aew1[r * 4 + c])  : __float2half(0.f);
        wh[WH_LCE1 + i] = (c < 6) ? __float2half(lcew1[r * 6 + c]) : __float2half(0.f);
    }
}

// ---------------- pad+convert u / lctx to half [MBIG x 8] ----------------
__global__ void conv_in_kernel(const float* __restrict__ u,
                               const float* __restrict__ lctx,
                               __half* __restrict__ uh,
                               __half* __restrict__ lch)
{
    int i = blockIdx.x * blockDim.x + threadIdx.x;
    if (i >= MBIG * 8) return;
    int r = i >> 3, c = i & 7;
    uh[i]  = (c < 4) ? __float2half(u[r * 4 + c])    : __float2half(0.f);
    lch[i] = (c < 6) ? __float2half(lctx[r * 6 + c]) : __float2half(0.f);
}

// ---------------- Whh transpose ----------------
__global__ void transpose_whh_kernel(const float* __restrict__ W,
                                     float* __restrict__ Wt)
{
    int idx = blockIdx.x * blockDim.x + threadIdx.x;
    if (idx >= GDIM * EMB) return;
    int c = idx / EMB, k = idx - c * EMB;
    Wt[k * GDIM + c] = W[idx];
}

// ---------------- persistent fused GRU scan ----------------
#define SCAN_CTAS    128
#define ROWS_PER     16
#define SCAN_THREADS 320
#define H2S_BYTES    (200 * 9 * 8)
#define GHS_BYTES    (600 * 18 * 4)
#define SCAN_SMEM    (H2S_BYTES + GHS_BYTES + 600 * 4)

__global__ void __launch_bounds__(SCAN_THREADS, 1)
scan_kernel(const float* __restrict__ Wt,
            const float* __restrict__ bhh,
            const __half* __restrict__ gih,
            const float* __restrict__ h0,
            __half* __restrict__ hidh)
{
    extern __shared__ char sm[];
    ull   (*h2s)[9]  = reinterpret_cast<ull(*)[9]>(sm);
    float (*ghs)[18] = reinterpret_cast<float(*)[18]>(sm + H2S_BYTES);
    float* bhh_s     = reinterpret_cast<float*>(sm + H2S_BYTES + GHS_BYTES);
    float* hsf       = reinterpret_cast<float*>(sm);

    const int tid = threadIdx.x;
    const int b0  = blockIdx.x * ROWS_PER;
    const float2* Wt2 = reinterpret_cast<const float2*>(Wt);

    for (int j = tid; j < GDIM; j += SCAN_THREADS) bhh_s[j] = bhh[j];
    for (int e = tid; e < ROWS_PER * EMB; e += SCAN_THREADS) {
        int r = e / EMB, j = e - r * EMB;
        hsf[j * 18 + r] = h0[(size_t)(b0 + r) * EMB + j];
    }
    __syncthreads();

    const bool active = (tid < 300);

    for (int t = 0; t < TST; t++) {
        if (active) {
            ull acc0[8], acc1[8];
#pragma unroll
            for (int p = 0; p < 8; p++) { acc0[p] = 0ull; acc1[p] = 0ull; }

            float2 wbuf[4];
#pragma unroll
            for (int i = 0; i < 4; i++) wbuf[i] = Wt2[i * 300 + tid];

#pragma unroll 4
            for (int k = 0; k < EMB; k++) {
                float2 w = wbuf[k & 3];
                if (k + 4 < EMB) wbuf[k & 3] = Wt2[(k + 4) * 300 + tid];
                ull w0 = pack2(w.x, w.x);
                ull w1 = pack2(w.y, w.y);
                ull h0v = h2s[k][0], h1v = h2s[k][1], h2v = h2s[k][2], h3v = h2s[k][3];
                ull h4v = h2s[k][4], h5v = h2s[k][5], h6v = h2s[k][6], h7v = h2s[k][7];
                acc0[0] = ffma2(h0v, w0, acc0[0]);  acc1[0] = ffma2(h0v, w1, acc1[0]);
                acc0[1] = ffma2(h1v, w0, acc0[1]);  acc1[1] = ffma2(h1v, w1, acc1[1]);
                acc0[2] = ffma2(h2v, w0, acc0[2]);  acc1[2] = ffma2(h2v, w1, acc1[2]);
                acc0[3] = ffma2(h3v, w0, acc0[3]);  acc1[3] = ffma2(h3v, w1, acc1[3]);
                acc0[4] = ffma2(h4v, w0, acc0[4]);  acc1[4] = ffma2(h4v, w1, acc1[4]);
                acc0[5] = ffma2(h5v, w0, acc0[5]);  acc1[5] = ffma2(h5v, w1, acc1[5]);
                acc0[6] = ffma2(h6v, w0, acc0[6]);  acc1[6] = ffma2(h6v, w1, acc1[6]);
                acc0[7] = ffma2(h7v, w0, acc0[7]);  acc1[7] = ffma2(h7v, w1, acc1[7]);
            }

            int c0 = 2 * tid, c1 = 2 * tid + 1;
            float2* g0 = reinterpret_cast<float2*>(&ghs[c0][0]);
            float2* g1 = reinterpret_cast<float2*>(&ghs[c1][0]);
#pragma unroll
            for (int p = 0; p < 8; p++) {
                g0[p] = unpack2(acc0[p]);
                g1[p] = unpack2(acc1[p]);
            }
        }
        __syncthreads();

        {
            const __half* gib = gih + ((size_t)t * BSZ + b0) * GDIM;
            __half* hout = hidh + ((size_t)(t + 1) * BSZ + b0) * EMB;
#pragma unroll
            for (int it = 0; it < (ROWS_PER * EMB) / SCAN_THREADS; it++) {
                int e = tid + it * SCAN_THREADS;
                int r = e / EMB, j = e - r * EMB;
                const __half* gr = gib + (size_t)r * GDIM;
                float gir = __half2float(gr[j]);
                float giz = __half2float(gr[j + 200]);
                float gin = __half2float(gr[j + 400]);
                float ghr = ghs[j][r]       + bhh_s[j];
                float ghz = ghs[j + 200][r] + bhh_s[j + 200];
                float ghn = ghs[j + 400][r] + bhh_s[j + 400];
                float rg = 1.f / (1.f + expf(-(gir + ghr)));
                float z  = 1.f / (1.f + expf(-(giz + ghz)));
                float n  = tanhf(gin + rg * ghn);
                float hold = hsf[j * 18 + r];
                float hnew = (1.f - z) * n + z * hold;
                hsf[j * 18 + r] = hnew;
                hout[(size_t)r * EMB + j] = __float2half(hnew);
            }
        }
        __syncthreads();
    }
}

// ---------------- fused 400 -> (12 mean, 12 std) projection (half input) ----------------
__global__ void proj2_kernel(const __half* __restrict__ T,
                             const float* __restrict__ decw2,
                             const float* __restrict__ decb2,
                             const float* __restrict__ covw2,
                             const float* __restrict__ covb2,
                             float* __restrict__ outM,
                             float* __restrict__ outS, int M)
{
    int warp = (blockIdx.x * blockDim.x + threadIdx.x) >> 5;
    int lane = threadIdx.x & 31;
    if (warp >= M) return;
    const __half* row = T + (size_t)warp * 400;
    float am[SDIM], as[SDIM];
#pragma unroll
    for (int s = 0; s < SDIM; s++) { am[s] = 0.f; as[s] = 0.f; }
    for (int k = lane; k < EMB; k += 32) {
        float t0 = __half2float(row[k]);
        float t1 = __half2float(row[200 + k]);
#pragma unroll
        for (int s = 0; s < SDIM; s++) {
            am[s] = fmaf(t0, decw2[s * EMB + k], am[s]);
            as[s] = fmaf(t1, covw2[s * EMB + k], as[s]);
        }
    }
#pragma unroll
    for (int s = 0; s < SDIM; s++) {
#pragma unroll
        for (int off = 16; off > 0; off >>= 1) {
            am[s] += __shfl_xor_sync(0xffffffffu, am[s], off);
            as[s] += __shfl_xor_sync(0xffffffffu, as[s], off);
        }
    }
    if (lane == 0) {
        float* om = outM + (size_t)warp * SDIM;
        float* os = outS + (size_t)warp * SDIM;
#pragma unroll
        for (int s = 0; s < SDIM; s++) {
            om[s] = am[s] + decb2[s];
            float v = as[s] + covb2[s];
            float sp = log1pf(expf(-fabsf(v))) + fmaxf(v, 0.f);
            os[s] = sqrtf(sp + EPSV);
        }
    }
}

// ---------------- host-side ----------------
static void launch_hm(int act, const __half* A, int lda, const __half* W, int ldw,
                      const float* bias, const float* base, int baseMask,
                      float* outF, int ldf, __half* outH, int ldh,
                      int M, int N, int K)
{
    dim3 grid((N + 127) / 128, M / 128);
    dim3 blk(HM_THREADS);
    size_t shm = HM_SMEM;
    if (base) {
        if (act == ACT_NONE)      hm_gemm<ACT_NONE, true><<<grid, blk, shm>>>(A, lda, W, ldw, bias, base, baseMask, outF, ldf, outH, ldh, M, N, K);
        else if (act == ACT_RELU) hm_gemm<ACT_RELU, true><<<grid, blk, shm>>>(A, lda, W, ldw, bias, base, baseMask, outF, ldf, outH, ldh, M, N, K);
        else                      hm_gemm<ACT_TANH, true><<<grid, blk, shm>>>(A, lda, W, ldw, bias, base, baseMask, outF, ldf, outH, ldh, M, N, K);
    } else {
        if (act == ACT_NONE)      hm_gemm<ACT_NONE, false><<<grid, blk, shm>>>(A, lda, W, ldw, bias, nullptr, 0, outF, ldf, outH, ldh, M, N, K);
        else if (act == ACT_RELU) hm_gemm<ACT_RELU, false><<<grid, blk, shm>>>(A, lda, W, ldw, bias, nullptr, 0, outF, ldf, outH, ldh, M, N, K);
        else                      hm_gemm<ACT_TANH, false><<<grid, blk, shm>>>(A, lda, W, ldw, bias, nullptr, 0, outF, ldf, outH, ldh, M, N, K);
    }
}

extern "C" void kernel_launch(void* const* d_in, const int* in_sizes, int n_in,
                              void* d_out, int out_size)
{
    const float* x        = (const float*)d_in[0];
    const float* u        = (const float*)d_in[1];
    const float* ctx_mean = (const float*)d_in[2];
    const float* lctx     = (const float*)d_in[3];
    const float* se_w1 = (const float*)d_in[4];  const float* se_b1 = (const float*)d_in[5];
    const float* se_w2 = (const float*)d_in[6];  const float* se_b2 = (const float*)d_in[7];
    const float* ae_w1 = (const float*)d_in[8];  const float* ae_b1 = (const float*)d_in[9];
    const float* ae_w2 = (const float*)d_in[10]; const float* ae_b2 = (const float*)d_in[11];
    const float* ce_w1 = (const float*)d_in[12]; const float* ce_b1 = (const float*)d_in[13];
    const float* ce_w2 = (const float*)d_in[14]; const float* ce_b2 = (const float*)d_in[15];
    const float* lce_w1 = (const float*)d_in[16]; const float* lce_b1 = (const float*)d_in[17];
    const float* lce_w2 = (const float*)d_in[18]; const float* lce_b2 = (const float*)d_in[19];
    const float* dec_w1 = (const float*)d_in[20]; const float* dec_b1 = (const float*)d_in[21];
    const float* dec_w2 = (const float*)d_in[22]; const float* dec_b2 = (const float*)d_in[23];
    const float* gru_wih = (const float*)d_in[24]; const float* gru_bih = (const float*)d_in[25];
    const float* gru_whh = (const float*)d_in[26]; const float* gru_bhh = (const float*)d_in[27];
    const float* cov_w1 = (const float*)d_in[28]; const float* cov_b1 = (const float*)d_in[29];
    const float* cov_w2 = (const float*)d_in[30]; const float* cov_b2 = (const float*)d_in[31];

    float  *p_gibase, *p_h0, *p_wt, *p_bdc;
    __half *p_h1h, *p_h1hb, *p_ctxh, *p_alch, *p_gih, *p_hidh, *p_tmph, *p_uh, *p_lch, *p_wh;
    cudaGetSymbolAddress((void**)&p_gibase, g_gibase);
    cudaGetSymbolAddress((void**)&p_h0,     g_h0);
    cudaGetSymbolAddress((void**)&p_wt,     g_whh_t);
    cudaGetSymbolAddress((void**)&p_bdc,    g_bdc);
    cudaGetSymbolAddress((void**)&p_h1h,    g_h1h);
    cudaGetSymbolAddress((void**)&p_h1hb,   g_h1hb);
    cudaGetSymbolAddress((void**)&p_ctxh,   g_ctxh);
    cudaGetSymbolAddress((void**)&p_alch,   g_alch);
    cudaGetSymbolAddress((void**)&p_gih,    g_gih);
    cudaGetSymbolAddress((void**)&p_hidh,   g_hidh);
    cudaGetSymbolAddress((void**)&p_tmph,   g_tmph);
    cudaGetSymbolAddress((void**)&p_uh,     g_uh);
    cudaGetSymbolAddress((void**)&p_lch,    g_lch);
    cudaGetSymbolAddress((void**)&p_wh,     g_wh);

    cudaFuncSetAttribute(scan_kernel, cudaFuncAttributeMaxDynamicSharedMemorySize, SCAN_SMEM);
    cudaFuncSetAttribute(hm_gemm_pair, cudaFuncAttributeMaxDynamicSharedMemorySize, HM_SMEM);
    cudaFuncSetAttribute(hm_gemm<ACT_NONE, true>,  cudaFuncAttributeMaxDynamicSharedMemorySize, HM_SMEM);
    cudaFuncSetAttribute(hm_gemm<ACT_RELU, true>,  cudaFuncAttributeMaxDynamicSharedMemorySize, HM_SMEM);
    cudaFuncSetAttribute(hm_gemm<ACT_TANH, true>,  cudaFuncAttributeMaxDynamicSharedMemorySize, HM_SMEM);
    cudaFuncSetAttribute(hm_gemm<ACT_NONE, false>, cudaFuncAttributeMaxDynamicSharedMemorySize, HM_SMEM);
    cudaFuncSetAttribute(hm_gemm<ACT_RELU, false>, cudaFuncAttributeMaxDynamicSharedMemorySize, HM_SMEM);
    cudaFuncSetAttribute(hm_gemm<ACT_TANH, false>, cudaFuncAttributeMaxDynamicSharedMemorySize, HM_SMEM);

    float* out_mean = (float*)d_out;
    float* out_std  = out_mean + (size_t)MROWS * SDIM;

    const int eb = 256;

    conv_w_kernel<<<(360000 + eb - 1) / eb, eb>>>(se_w2, ce_w2, ae_w2, lce_w2,
                                                  dec_w1, cov_w1, gru_wih, p_wh,
                                                  dec_b1, cov_b1, p_bdc,
                                                  ae_w1, lce_w1);
    conv_in_kernel<<<(MBIG * 8 + eb - 1) / eb, eb>>>(u, lctx, p_uh, p_lch);
    transpose_whh_kernel<<<(GDIM * EMB + eb - 1) / eb, eb>>>(gru_whh, p_wt);

    // state_embed -> h0 (fp32 for scan) + hidh block 0 (half for dec/cov)
    embed1_kernel<<<(BSZ * EMB + eb - 1) / eb, eb>>>(x, se_w1, se_b1, p_h1h, BSZ, SDIM);
    launch_hm(ACT_TANH, p_h1h, EMB, p_wh + WH_SE, EMB, se_b2, nullptr, 0,
              p_h0, EMB, p_hidh, EMB, BSZ, EMB, EMB);

    // ctx_embed (half), then gi_base (fp32)
    embed1_kernel<<<(BSZ * EMB + eb - 1) / eb, eb>>>(ctx_mean, ce_w1, ce_b1, p_h1h, BSZ, 8);
    launch_hm(ACT_RELU, p_h1h, EMB, p_wh + WH_CE, EMB, ce_b2, nullptr, 0,
              nullptr, 0, p_ctxh, EMB, BSZ, EMB, EMB);
    launch_hm(ACT_NONE, p_ctxh, EMB, p_wh + WH_WIH, GDIM, gru_bih, nullptr, 0,
              p_gibase, GDIM, nullptr, 0, BSZ, GDIM, EMB);

    // paired layer-1: ae (u) -> h1h, lce (lctx) -> h1hb  (K=8, one launch, z=2)
    {
        dim3 grid((EMB + 127) / 128, MBIG / 128, 2);
        hm_gemm_pair<<<grid, HM_THREADS, HM_SMEM>>>(
            p_uh,  p_wh + WH_AE1,  ae_b1,  p_h1h,
            p_lch, p_wh + WH_LCE1, lce_b1, p_h1hb,
            8, 8, EMB, MBIG, EMB, 8);
    }
    // paired layer-2: ae -> alc[:,0:200], lce -> alc[:,200:400]  (K=200, one launch, z=2)
    {
        dim3 grid((EMB + 127) / 128, MBIG / 128, 2);
        hm_gemm_pair<<<grid, HM_THREADS, HM_SMEM>>>(
            p_h1h,  p_wh + WH_AE,  ae_b2,  p_alch,
            p_h1hb, p_wh + WH_LCE, lce_b2, p_alch + 200,
            EMB, EMB, 400, MBIG, EMB, EMB);
    }

    // gi = [a|lc] @ Wih[:,200:600]^T + gi_base  (half out)
    launch_hm(ACT_NONE, p_alch, 400, p_wh + WH_WIH + 200, GDIM, nullptr, p_gibase, BSZ - 1,
              nullptr, 0, p_gih, GDIM, MBIG, GDIM, 400);

    // fused persistent GRU scan
    scan_kernel<<<SCAN_CTAS, SCAN_THREADS, SCAN_SMEM>>>(p_wt, gru_bhh, p_gih, p_h0, p_hidh);

    // fused dec|cov hidden layer: tmph[M][400] (half)
    launch_hm(ACT_RELU, p_hidh, EMB, p_wh + WH_DEC, EMB, p_bdc, nullptr, 0,
              nullptr, 0, p_tmph, 400, MROWS, 400, EMB);

    // fused projection: mean + std
    {
        int blocks = (MROWS * 32 + 255) / 256;
        proj2_kernel<<<blocks, 256>>>(p_tmph, dec_w2, dec_b2, cov_w2, cov_b2,
                                      out_mean, out_std, MROWS);
    }

    (void)in_sizes; (void)n_in; (void)out_size;
}

// round 15
// speedup vs baseline: 1.0848x; 1.0848x over previous
#include <cuda_runtime.h>
#include <cuda_fp16.h>
#include <cstdint>

// ---------------- problem dims ----------------
#define BSZ   2048
#define TST   100
#define EMB   200
#define SDIM  12
#define GDIM  600            // 3*EMB
#define MBIG  (TST*BSZ)      // 204800 rows
#define MROWS ((TST+1)*BSZ)  // 206848 rows
#define EPSV  1e-4f

typedef unsigned long long ull;

__device__ __forceinline__ ull ffma2(ull a, ull b, ull c) {
    ull d;
    asm("fma.rn.f32x2 %0, %1, %2, %3;" : "=l"(d) : "l"(a), "l"(b), "l"(c));
    return d;
}
__device__ __forceinline__ ull pack2(float lo, float hi) {
    ull d;
    asm("mov.b64 %0, {%1, %2};" : "=l"(d) : "f"(lo), "f"(hi));
    return d;
}
__device__ __forceinline__ float2 unpack2(ull v) {
    float2 r;
    asm("mov.b64 {%0, %1}, %2;" : "=f"(r.x), "=f"(r.y) : "l"(v));
    return r;
}
__device__ __forceinline__ uint32_t smem_u32(const void* p) {
    uint32_t a;
    asm("{ .reg .u64 t; cvta.to.shared.u64 t, %1; cvt.u32.u64 %0, t; }" : "=r"(a) : "l"(p));
    return a;
}

// mma.sync m16n8k16 f16 -> f32 accum
__device__ __forceinline__ void mma_f16(float c[4],
                                        uint32_t a0, uint32_t a1, uint32_t a2, uint32_t a3,
                                        uint32_t b0, uint32_t b1) {
    asm volatile(
        "mma.sync.aligned.m16n8k16.row.col.f32.f16.f16.f32 "
        "{%0,%1,%2,%3}, {%4,%5,%6,%7}, {%8,%9}, {%0,%1,%2,%3};"
        : "+f"(c[0]), "+f"(c[1]), "+f"(c[2]), "+f"(c[3])
        : "r"(a0), "r"(a1), "r"(a2), "r"(a3), "r"(b0), "r"(b1));
}

__device__ __forceinline__ void ldsm_x4(uint32_t& r0, uint32_t& r1, uint32_t& r2, uint32_t& r3,
                                        uint32_t addr) {
    asm volatile("ldmatrix.sync.aligned.m8n8.x4.shared.b16 {%0,%1,%2,%3}, [%4];"
                 : "=r"(r0), "=r"(r1), "=r"(r2), "=r"(r3) : "r"(addr));
}

__device__ __forceinline__ void cp16h(uint32_t daddr, const __half* src, uint32_t bytes) {
    asm volatile("cp.async.ca.shared.global [%0], [%1], 16, %2;"
                 :: "r"(daddr), "l"(src), "r"(bytes));
}
#define CP_COMMIT()  asm volatile("cp.async.commit_group;" ::: "memory")
#define CP_WAIT_1()  asm volatile("cp.async.wait_group 1;" ::: "memory")
#define CP_WAIT_0()  asm volatile("cp.async.wait_group 0;" ::: "memory")

// ---------------- device scratch ----------------
__device__ __align__(128) float  g_gibase[BSZ * GDIM];
__device__ __align__(128) float  g_h0[BSZ * EMB];
__device__ __align__(128) float  g_whh_t[EMB * GDIM];
__device__ __align__(128) float  g_bdc[400];                      // packed dec_b1|cov_b1
__device__ __align__(128) __half g_h1h[(size_t)MBIG * EMB];
__device__ __align__(128) __half g_ctxh[BSZ * EMB];
__device__ __align__(128) __half g_alch[(size_t)MBIG * 400];
__device__ __align__(128) __half g_gih[(size_t)MBIG * GDIM];
__device__ __align__(128) __half g_hidh[(size_t)MROWS * EMB];
__device__ __align__(128) __half g_tmph[(size_t)MROWS * 400];     // fused dec|cov hidden (half)
__device__ __align__(128) __half g_uh[(size_t)MBIG * 8];          // padded half u
__device__ __align__(128) __half g_lch[(size_t)MBIG * 8];         // padded half lctx
__device__ __align__(128) __half g_wh[604000];

#define WH_SE   0
#define WH_CE   40000
#define WH_AE   80000
#define WH_LCE  120000
#define WH_DEC  160000      // dec_w1 rows 0-199 ...
#define WH_COV  200000      // ... cov_w1 rows 200-399 (contiguous => [400][200])
#define WH_WIH  240000      // 600x600
#define WH_AE1  600000      // ae_w1 padded [200][8]
#define WH_LCE1 601600      // lce_w1 padded [200][8]

// ---------------- fp16 tensor-core GEMM (round-11 proven config) ----------------
#define ROWB      144                 // bytes per smem tile row (64 halves + 8 pad)
#define TILE_B    (128 * ROWB)        // 18432
#define BUF_B     (2 * TILE_B)        // 36864
#define HM_SMEM   (2 * BUF_B)         // 73728

enum { ACT_NONE = 0, ACT_RELU = 1, ACT_TANH = 2 };

// stage [128 rows x 64 halves] via cp.async (zero-fills beyond K / rows)
__device__ __forceinline__ void stage_h64(uint32_t sbase, const __half* __restrict__ src,
                                          int ld, int row0, int rowsValid,
                                          int k0, int K, int tid)
{
#pragma unroll
    for (int pass = 0; pass < 4; pass++) {
        int e = tid + pass * 256;
        int r = e >> 3, c = e & 7;
        int ks = k0 + c * 8;
        int valid = (r < rowsValid) ? min(max((K - ks) * 2, 0), 16) : 0;
        const __half* g = src + (size_t)(row0 + ((r < rowsValid) ? r : 0)) * ld + (valid ? ks : 0);
        cp16h(sbase + (uint32_t)(r * ROWB + c * 16), g, (uint32_t)valid);
    }
}

template <int ACT, bool HAS_BASE>
__global__ void __launch_bounds__(256, 2)
hm_gemm(const __half* __restrict__ A, int lda,
        const __half* __restrict__ W, int ldw,
        const float* __restrict__ bias,
        const float* __restrict__ base, int baseMask,
        float* __restrict__ outF, int ldf,
        __half* __restrict__ outH, int ldh,
        int M, int N, int K)
{
    extern __shared__ char smh[];
    const uint32_t smem_base = smem_u32(smh);

    const int tid  = threadIdx.x;
    const int wid  = tid >> 5;
    const int lane = tid & 31;
    const int warp_m = wid >> 1;
    const int warp_n = wid & 1;
    const int bm = blockIdx.y * 128;
    const int bn = blockIdx.x * 128;
    const int nValid = min(128, N - bn);

    const int lg = lane >> 2;
    const int lt = lane & 3;

    const uint32_t aRow = (uint32_t)(warp_m * 32 + (lane & 15));
    const uint32_t aOff = aRow * ROWB + ((lane >> 4) << 3) * 2;
    const uint32_t bRow = (uint32_t)(warp_n * 64 + ((lane >> 4) & 1) * 8 + (lane & 7));
    const uint32_t bOff = bRow * ROWB + (((lane >> 3) & 1) << 3) * 2;

    float acc[2][8][4];
#pragma unroll
    for (int mt = 0; mt < 2; mt++)
#pragma unroll
        for (int nt = 0; nt < 8; nt++)
#pragma unroll
            for (int j = 0; j < 4; j++) acc[mt][nt][j] = 0.f;

    const int nk = (K + 63) / 64;

    stage_h64(smem_base,          A, lda, bm, 128,    0, K, tid);
    stage_h64(smem_base + TILE_B, W, ldw, bn, nValid, 0, K, tid);
    CP_COMMIT();

    for (int kc = 0; kc < nk; kc++) {
        if (kc + 1 < nk) {
            uint32_t nb = smem_base + (uint32_t)(((kc + 1) & 1) * BUF_B);
            int k0n = (kc + 1) * 64;
            stage_h64(nb,          A, lda, bm, 128,    k0n, K, tid);
            stage_h64(nb + TILE_B, W, ldw, bn, nValid, k0n, K, tid);
            CP_COMMIT();
            CP_WAIT_1();
        } else {
            CP_WAIT_0();
        }
        __syncthreads();

        const uint32_t aBase = smem_base + (uint32_t)((kc & 1) * BUF_B) + aOff;
        const uint32_t bBase = smem_base + (uint32_t)((kc & 1) * BUF_B) + TILE_B + bOff;

        const int kRem = K - kc * 64;
        const int kkmax = min(4, (kRem + 15) >> 4);

#pragma unroll 4
        for (int kk = 0; kk < kkmax; kk++) {
            const uint32_t kByte = (uint32_t)(kk * 32);
            uint32_t af[2][4];
            ldsm_x4(af[0][0], af[0][1], af[0][2], af[0][3], aBase + kByte);
            ldsm_x4(af[1][0], af[1][1], af[1][2], af[1][3], aBase + 16 * ROWB + kByte);
#pragma unroll
            for (int p = 0; p < 4; p++) {
                uint32_t b00, b01, b10, b11;
                ldsm_x4(b00, b01, b10, b11, bBase + (uint32_t)(p * 16 * ROWB) + kByte);
                mma_f16(acc[0][2 * p],     af[0][0], af[0][1], af[0][2], af[0][3], b00, b01);
                mma_f16(acc[1][2 * p],     af[1][0], af[1][1], af[1][2], af[1][3], b00, b01);
                mma_f16(acc[0][2 * p + 1], af[0][0], af[0][1], af[0][2], af[0][3], b10, b11);
                mma_f16(acc[1][2 * p + 1], af[1][0], af[1][1], af[1][2], af[1][3], b10, b11);
            }
        }
        __syncthreads();
    }

#pragma unroll
    for (int mt = 0; mt < 2; mt++) {
        int gm0 = bm + warp_m * 32 + mt * 16 + lg;
        const float* base0 = HAS_BASE ? (base + (size_t)(gm0 & baseMask) * GDIM) : nullptr;
        const float* base1 = HAS_BASE ? (base + (size_t)((gm0 + 8) & baseMask) * GDIM) : nullptr;
#pragma unroll
        for (int nt = 0; nt < 8; nt++) {
            int gnl = warp_n * 64 + nt * 8 + lt * 2;
            if (gnl >= nValid) continue;
            int gn = bn + gnl;
            float b0v = bias ? bias[gn]     : 0.f;
            float b1v = bias ? bias[gn + 1] : 0.f;
            float v00 = acc[mt][nt][0] + b0v;
            float v01 = acc[mt][nt][1] + b1v;
            float v10 = acc[mt][nt][2] + b0v;
            float v11 = acc[mt][nt][3] + b1v;
            if (HAS_BASE) {
                v00 += base0[gn]; v01 += base0[gn + 1];
                v10 += base1[gn]; v11 += base1[gn + 1];
            }
            if (ACT == ACT_RELU) {
                v00 = fmaxf(v00, 0.f); v01 = fmaxf(v01, 0.f);
                v10 = fmaxf(v10, 0.f); v11 = fmaxf(v11, 0.f);
            } else if (ACT == ACT_TANH) {
                v00 = tanhf(v00); v01 = tanhf(v01);
                v10 = tanhf(v10); v11 = tanhf(v11);
            }
            if (outF) {
                *reinterpret_cast<float2*>(outF + (size_t)gm0 * ldf + gn)       = make_float2(v00, v01);
                *reinterpret_cast<float2*>(outF + (size_t)(gm0 + 8) * ldf + gn) = make_float2(v10, v11);
            }
            if (outH) {
                *reinterpret_cast<__half2*>(outH + (size_t)gm0 * ldh + gn)       = __floats2half2_rn(v00, v01);
                *reinterpret_cast<__half2*>(outH + (size_t)(gm0 + 8) * ldh + gn) = __floats2half2_rn(v10, v11);
            }
        }
    }
}

// ---------------- tiny-K first layer (half output; small M only) ----------------
__global__ void embed1_kernel(const float* __restrict__ X,
                              const float* __restrict__ W,
                              const float* __restrict__ B,
                              __half* __restrict__ Y, int M, int K)
{
    int idx = blockIdx.x * blockDim.x + threadIdx.x;
    if (idx >= M * EMB) return;
    int m = idx / EMB, j = idx - m * EMB;
    const float* xr = X + (size_t)m * K;
    const float* wr = W + (size_t)j * K;
    float s = B[j];
    for (int k = 0; k < K; k++) s = fmaf(xr[k], wr[k], s);
    Y[idx] = __float2half(fmaxf(s, 0.f));
}

// ---------------- convert weights to half (+ padded layer-1 weights, dec|cov bias) ----------------
__global__ void conv_w_kernel(const float* __restrict__ se, const float* __restrict__ ce,
                              const float* __restrict__ ae, const float* __restrict__ lce,
                              const float* __restrict__ dec, const float* __restrict__ cov,
                              const float* __restrict__ wih, __half* __restrict__ wh,
                              const float* __restrict__ decb, const float* __restrict__ covb,
                              float* __restrict__ bdc,
                              const float* __restrict__ aew1, const float* __restrict__ lcew1)
{
    int i = blockIdx.x * blockDim.x + threadIdx.x;
    if (i < 40000) {
        wh[WH_SE  + i] = __float2half(se[i]);
        wh[WH_CE  + i] = __float2half(ce[i]);
        wh[WH_AE  + i] = __float2half(ae[i]);
        wh[WH_LCE + i] = __float2half(lce[i]);
        wh[WH_DEC + i] = __float2half(dec[i]);
        wh[WH_COV + i] = __float2half(cov[i]);
    }
    if (i < 360000) wh[WH_WIH + i] = __float2half(wih[i]);
    if (i < 200) {
        bdc[i]       = decb[i];
        bdc[200 + i] = covb[i];
    }
    if (i < 1600) {
        int r = i >> 3, c = i & 7;
        wh[WH_AE1  + i] = (c < 4) ? __float2half(aew1[r * 4 + c])  : __float2half(0.f);
        wh[WH_LCE1 + i] = (c < 6) ? __float2half(lcew1[r * 6 + c]) : __float2half(0.f);
    }
}

// ---------------- pad+convert u / lctx to half [MBIG x 8] ----------------
__global__ void conv_in_kernel(const float* __restrict__ u,
                               const float* __restrict__ lctx,
                               __half* __restrict__ uh,
                               __half* __restrict__ lch)
{
    int i = blockIdx.x * blockDim.x + threadIdx.x;
    if (i >= MBIG * 8) return;
    int r = i >> 3, c = i & 7;
    uh[i]  = (c < 4) ? __float2half(u[r * 4 + c])    : __float2half(0.f);
    lch[i] = (c < 6) ? __float2half(lctx[r * 6 + c]) : __float2half(0.f);
}

// ---------------- Whh transpose ----------------
__global__ void transpose_whh_kernel(const float* __restrict__ W,
                                     float* __restrict__ Wt)
{
    int idx = blockIdx.x * blockDim.x + threadIdx.x;
    if (idx >= GDIM * EMB) return;
    int c = idx / EMB, k = idx - c * EMB;
    Wt[k * GDIM + c] = W[idx];
}

// ---------------- persistent fused GRU scan: 256 CTAs x 8 rows, 2 CTAs/SM ----------------
#define SCAN_CTAS    256
#define ROWS_PER     8
#define SCAN_THREADS 320
#define H2S_BYTES    (200 * 5 * 8)      // 8000: [200][4 pairs + 1 pad] ull
#define GHS_BYTES    (600 * 10 * 4)     // 24000: [600][8 + 2 pad] float
#define SCAN_SMEM    (H2S_BYTES + GHS_BYTES + 600 * 4)   // 34400

__global__ void __launch_bounds__(SCAN_THREADS, 2)
scan_kernel(const float* __restrict__ Wt,
            const float* __restrict__ bhh,
            const __half* __restrict__ gih,
            const float* __restrict__ h0,
            __half* __restrict__ hidh)
{
    extern __shared__ char sm[];
    ull   (*h2s)[5]  = reinterpret_cast<ull(*)[5]>(sm);
    float (*ghs)[10] = reinterpret_cast<float(*)[10]>(sm + H2S_BYTES);
    float* bhh_s     = reinterpret_cast<float*>(sm + H2S_BYTES + GHS_BYTES);
    float* hsf       = reinterpret_cast<float*>(sm);    // float view, row stride 10

    const int tid = threadIdx.x;
    const int b0  = blockIdx.x * ROWS_PER;
    const float2* Wt2 = reinterpret_cast<const float2*>(Wt);

    for (int j = tid; j < GDIM; j += SCAN_THREADS) bhh_s[j] = bhh[j];
    for (int e = tid; e < ROWS_PER * EMB; e += SCAN_THREADS) {
        int r = e / EMB, j = e - r * EMB;
        hsf[j * 10 + r] = h0[(size_t)(b0 + r) * EMB + j];
    }
    __syncthreads();

    const bool active = (tid < 300);

    for (int t = 0; t < TST; t++) {
        // ---- gh = h @ Whh^T : thread owns cols (2t,2t+1), 4 row-pairs ----
        if (active) {
            ull acc0[4], acc1[4];
#pragma unroll
            for (int p = 0; p < 4; p++) { acc0[p] = 0ull; acc1[p] = 0ull; }

            float2 wbuf[4];
#pragma unroll
            for (int i = 0; i < 4; i++) wbuf[i] = Wt2[i * 300 + tid];

#pragma unroll 4
            for (int k = 0; k < EMB; k++) {
                float2 w = wbuf[k & 3];
                if (k + 4 < EMB) wbuf[k & 3] = Wt2[(k + 4) * 300 + tid];
                ull w0 = pack2(w.x, w.x);
                ull w1 = pack2(w.y, w.y);
                ull h0v = h2s[k][0], h1v = h2s[k][1], h2v = h2s[k][2], h3v = h2s[k][3];
                acc0[0] = ffma2(h0v, w0, acc0[0]);  acc1[0] = ffma2(h0v, w1, acc1[0]);
                acc0[1] = ffma2(h1v, w0, acc0[1]);  acc1[1] = ffma2(h1v, w1, acc1[1]);
                acc0[2] = ffma2(h2v, w0, acc0[2]);  acc1[2] = ffma2(h2v, w1, acc1[2]);
                acc0[3] = ffma2(h3v, w0, acc0[3]);  acc1[3] = ffma2(h3v, w1, acc1[3]);
            }

            int c0 = 2 * tid, c1 = 2 * tid + 1;
            float2* g0 = reinterpret_cast<float2*>(&ghs[c0][0]);
            float2* g1 = reinterpret_cast<float2*>(&ghs[c1][0]);
#pragma unroll
            for (int p = 0; p < 4; p++) {
                g0[p] = unpack2(acc0[p]);
                g1[p] = unpack2(acc1[p]);
            }
        }
        __syncthreads();

        // ---- gate combine + in-place h update + global (half) store ----
        {
            const __half* gib = gih + ((size_t)t * BSZ + b0) * GDIM;
            __half* hout = hidh + ((size_t)(t + 1) * BSZ + b0) * EMB;
#pragma unroll
            for (int it = 0; it < (ROWS_PER * EMB) / SCAN_THREADS; it++) {
                int e = tid + it * SCAN_THREADS;
                int r = e / EMB, j = e - r * EMB;
                const __half* gr = gib + (size_t)r * GDIM;
                float gir = __half2float(gr[j]);
                float giz = __half2float(gr[j + 200]);
                float gin = __half2float(gr[j + 400]);
                float ghr = ghs[j][r]       + bhh_s[j];
                float ghz = ghs[j + 200][r] + bhh_s[j + 200];
                float ghn = ghs[j + 400][r] + bhh_s[j + 400];
                float rg = 1.f / (1.f + expf(-(gir + ghr)));
                float z  = 1.f / (1.f + expf(-(giz + ghz)));
                float n  = tanhf(gin + rg * ghn);
                float hold = hsf[j * 10 + r];
                float hnew = (1.f - z) * n + z * hold;
                hsf[j * 10 + r] = hnew;
                hout[(size_t)r * EMB + j] = __float2half(hnew);
            }
        }
        __syncthreads();
    }
}

// ---------------- fused 400 -> (12 mean, 12 std) projection (half input) ----------------
__global__ void proj2_kernel(const __half* __restrict__ T,
                             const float* __restrict__ decw2,
                             const float* __restrict__ decb2,
                             const float* __restrict__ covw2,
                             const float* __restrict__ covb2,
                             float* __restrict__ outM,
                             float* __restrict__ outS, int M)
{
    int warp = (blockIdx.x * blockDim.x + threadIdx.x) >> 5;
    int lane = threadIdx.x & 31;
    if (warp >= M) return;
    const __half* row = T + (size_t)warp * 400;
    float am[SDIM], as[SDIM];
#pragma unroll
    for (int s = 0; s < SDIM; s++) { am[s] = 0.f; as[s] = 0.f; }
    for (int k = lane; k < EMB; k += 32) {
        float t0 = __half2float(row[k]);
        float t1 = __half2float(row[200 + k]);
#pragma unroll
        for (int s = 0; s < SDIM; s++) {
            am[s] = fmaf(t0, decw2[s * EMB + k], am[s]);
            as[s] = fmaf(t1, covw2[s * EMB + k], as[s]);
        }
    }
#pragma unroll
    for (int s = 0; s < SDIM; s++) {
#pragma unroll
        for (int off = 16; off > 0; off >>= 1) {
            am[s] += __shfl_xor_sync(0xffffffffu, am[s], off);
            as[s] += __shfl_xor_sync(0xffffffffu, as[s], off);
        }
    }
    if (lane == 0) {
        float* om = outM + (size_t)warp * SDIM;
        float* os = outS + (size_t)warp * SDIM;
#pragma unroll
        for (int s = 0; s < SDIM; s++) {
            om[s] = am[s] + decb2[s];
            float v = as[s] + covb2[s];
            float sp = log1pf(expf(-fabsf(v))) + fmaxf(v, 0.f);
            os[s] = sqrtf(sp + EPSV);
        }
    }
}

// ---------------- host-side ----------------
static void launch_hm(int act, const __half* A, int lda, const __half* W, int ldw,
                      const float* bias, const float* base, int baseMask,
                      float* outF, int ldf, __half* outH, int ldh,
                      int M, int N, int K)
{
    dim3 grid((N + 127) / 128, M / 128);
    dim3 blk(256);
    size_t shm = HM_SMEM;
    if (base) {
        if (act == ACT_NONE)      hm_gemm<ACT_NONE, true><<<grid, blk, shm>>>(A, lda, W, ldw, bias, base, baseMask, outF, ldf, outH, ldh, M, N, K);
        else if (act == ACT_RELU) hm_gemm<ACT_RELU, true><<<grid, blk, shm>>>(A, lda, W, ldw, bias, base, baseMask, outF, ldf, outH, ldh, M, N, K);
        else                      hm_gemm<ACT_TANH, true><<<grid, blk, shm>>>(A, lda, W, ldw, bias, base, baseMask, outF, ldf, outH, ldh, M, N, K);
    } else {
        if (act == ACT_NONE)      hm_gemm<ACT_NONE, false><<<grid, blk, shm>>>(A, lda, W, ldw, bias, nullptr, 0, outF, ldf, outH, ldh, M, N, K);
        else if (act == ACT_RELU) hm_gemm<ACT_RELU, false><<<grid, blk, shm>>>(A, lda, W, ldw, bias, nullptr, 0, outF, ldf, outH, ldh, M, N, K);
        else                      hm_gemm<ACT_TANH, false><<<grid, blk, shm>>>(A, lda, W, ldw, bias, nullptr, 0, outF, ldf, outH, ldh, M, N, K);
    }
}

extern "C" void kernel_launch(void* const* d_in, const int* in_sizes, int n_in,
                              void* d_out, int out_size)
{
    const float* x        = (const float*)d_in[0];
    const float* u        = (const float*)d_in[1];
    const float* ctx_mean = (const float*)d_in[2];
    const float* lctx     = (const float*)d_in[3];
    const float* se_w1 = (const float*)d_in[4];  const float* se_b1 = (const float*)d_in[5];
    const float* se_w2 = (const float*)d_in[6];  const float* se_b2 = (const float*)d_in[7];
    const float* ae_w1 = (const float*)d_in[8];  const float* ae_b1 = (const float*)d_in[9];
    const float* ae_w2 = (const float*)d_in[10]; const float* ae_b2 = (const float*)d_in[11];
    const float* ce_w1 = (const float*)d_in[12]; const float* ce_b1 = (const float*)d_in[13];
    const float* ce_w2 = (const float*)d_in[14]; const float* ce_b2 = (const float*)d_in[15];
    const float* lce_w1 = (const float*)d_in[16]; const float* lce_b1 = (const float*)d_in[17];
    const float* lce_w2 = (const float*)d_in[18]; const float* lce_b2 = (const float*)d_in[19];
    const float* dec_w1 = (const float*)d_in[20]; const float* dec_b1 = (const float*)d_in[21];
    const float* dec_w2 = (const float*)d_in[22]; const float* dec_b2 = (const float*)d_in[23];
    const float* gru_wih = (const float*)d_in[24]; const float* gru_bih = (const float*)d_in[25];
    const float* gru_whh = (const float*)d_in[26]; const float* gru_bhh = (const float*)d_in[27];
    const float* cov_w1 = (const float*)d_in[28]; const float* cov_b1 = (const float*)d_in[29];
    const float* cov_w2 = (const float*)d_in[30]; const float* cov_b2 = (const float*)d_in[31];

    float  *p_gibase, *p_h0, *p_wt, *p_bdc;
    __half *p_h1h, *p_ctxh, *p_alch, *p_gih, *p_hidh, *p_tmph, *p_uh, *p_lch, *p_wh;
    cudaGetSymbolAddress((void**)&p_gibase, g_gibase);
    cudaGetSymbolAddress((void**)&p_h0,     g_h0);
    cudaGetSymbolAddress((void**)&p_wt,     g_whh_t);
    cudaGetSymbolAddress((void**)&p_bdc,    g_bdc);
    cudaGetSymbolAddress((void**)&p_h1h,    g_h1h);
    cudaGetSymbolAddress((void**)&p_ctxh,   g_ctxh);
    cudaGetSymbolAddress((void**)&p_alch,   g_alch);
    cudaGetSymbolAddress((void**)&p_gih,    g_gih);
    cudaGetSymbolAddress((void**)&p_hidh,   g_hidh);
    cudaGetSymbolAddress((void**)&p_tmph,   g_tmph);
    cudaGetSymbolAddress((void**)&p_uh,     g_uh);
    cudaGetSymbolAddress((void**)&p_lch,    g_lch);
    cudaGetSymbolAddress((void**)&p_wh,     g_wh);

    cudaFuncSetAttribute(scan_kernel, cudaFuncAttributeMaxDynamicSharedMemorySize, SCAN_SMEM);
    cudaFuncSetAttribute(hm_gemm<ACT_NONE, true>,  cudaFuncAttributeMaxDynamicSharedMemorySize, HM_SMEM);
    cudaFuncSetAttribute(hm_gemm<ACT_RELU, true>,  cudaFuncAttributeMaxDynamicSharedMemorySize, HM_SMEM);
    cudaFuncSetAttribute(hm_gemm<ACT_TANH, true>,  cudaFuncAttributeMaxDynamicSharedMemorySize, HM_SMEM);
    cudaFuncSetAttribute(hm_gemm<ACT_NONE, false>, cudaFuncAttributeMaxDynamicSharedMemorySize, HM_SMEM);
    cudaFuncSetAttribute(hm_gemm<ACT_RELU, false>, cudaFuncAttributeMaxDynamicSharedMemorySize, HM_SMEM);
    cudaFuncSetAttribute(hm_gemm<ACT_TANH, false>, cudaFuncAttributeMaxDynamicSharedMemorySize, HM_SMEM);

    float* out_mean = (float*)d_out;
    float* out_std  = out_mean + (size_t)MROWS * SDIM;

    const int eb = 256;

    conv_w_kernel<<<(360000 + eb - 1) / eb, eb>>>(se_w2, ce_w2, ae_w2, lce_w2,
                                                  dec_w1, cov_w1, gru_wih, p_wh,
                                                  dec_b1, cov_b1, p_bdc,
                                                  ae_w1, lce_w1);
    conv_in_kernel<<<(MBIG * 8 + eb - 1) / eb, eb>>>(u, lctx, p_uh, p_lch);
    transpose_whh_kernel<<<(GDIM * EMB + eb - 1) / eb, eb>>>(gru_whh, p_wt);

    // state_embed -> h0 (fp32 for scan) + hidh block 0 (half for dec/cov)
    embed1_kernel<<<(BSZ * EMB + eb - 1) / eb, eb>>>(x, se_w1, se_b1, p_h1h, BSZ, SDIM);
    launch_hm(ACT_TANH, p_h1h, EMB, p_wh + WH_SE, EMB, se_b2, nullptr, 0,
              p_h0, EMB, p_hidh, EMB, BSZ, EMB, EMB);

    // ctx_embed (half), then gi_base (fp32)
    embed1_kernel<<<(BSZ * EMB + eb - 1) / eb, eb>>>(ctx_mean, ce_w1, ce_b1, p_h1h, BSZ, 8);
    launch_hm(ACT_RELU, p_h1h, EMB, p_wh + WH_CE, EMB, ce_b2, nullptr, 0,
              nullptr, 0, p_ctxh, EMB, BSZ, EMB, EMB);
    launch_hm(ACT_NONE, p_ctxh, EMB, p_wh + WH_WIH, GDIM, gru_bih, nullptr, 0,
              p_gibase, GDIM, nullptr, 0, BSZ, GDIM, EMB);

    // action embed layer1 (tensor-core, K=8) -> h1h, then layer2 -> alc[:, 0:200]
    launch_hm(ACT_RELU, p_uh, 8, p_wh + WH_AE1, 8, ae_b1, nullptr, 0,
              nullptr, 0, p_h1h, EMB, MBIG, EMB, 8);
    launch_hm(ACT_RELU, p_h1h, EMB, p_wh + WH_AE, EMB, ae_b2, nullptr, 0,
              nullptr, 0, p_alch, 400, MBIG, EMB, EMB);

    // local ctx embed layer1 (tensor-core, K=8) -> h1h, then layer2 -> alc[:, 200:400]
    launch_hm(ACT_RELU, p_lch, 8, p_wh + WH_LCE1, 8, lce_b1, nullptr, 0,
              nullptr, 0, p_h1h, EMB, MBIG, EMB, 8);
    launch_hm(ACT_RELU, p_h1h, EMB, p_wh + WH_LCE, EMB, lce_b2, nullptr, 0,
              nullptr, 0, p_alch + 200, 400, MBIG, EMB, EMB);

    // gi = [a|lc] @ Wih[:,200:600]^T + gi_base  (half out)
    launch_hm(ACT_NONE, p_alch, 400, p_wh + WH_WIH + 200, GDIM, nullptr, p_gibase, BSZ - 1,
              nullptr, 0, p_gih, GDIM, MBIG, GDIM, 400);

    // fused persistent GRU scan (256 CTAs, 2/SM)
    scan_kernel<<<SCAN_CTAS, SCAN_THREADS, SCAN_SMEM>>>(p_wt, gru_bhh, p_gih, p_h0, p_hidh);

    // fused dec|cov hidden layer: tmph[M][400] (half)
    launch_hm(ACT_RELU, p_hidh, EMB, p_wh + WH_DEC, EMB, p_bdc, nullptr, 0,
              nullptr, 0, p_tmph, 400, MROWS, 400, EMB);

    // fused projection: mean + std
    {
        int blocks = (MROWS * 32 + 255) / 256;
        proj2_kernel<<<blocks, 256>>>(p_tmph, dec_w2, dec_b2, cov_w2, cov_b2,
                                      out_mean, out_std, MROWS);
    }

    (void)in_sizes; (void)n_in; (void)out_size;
}

// round 16
// speedup vs baseline: 1.1637x; 1.0728x over previous
#include <cuda_runtime.h>
#include <cuda_fp16.h>
#include <cstdint>

// ---------------- problem dims ----------------
#define BSZ   2048
#define TST   100
#define EMB   200
#define SDIM  12
#define GDIM  600            // 3*EMB
#define MBIG  (TST*BSZ)      // 204800 rows
#define MROWS ((TST+1)*BSZ)  // 206848 rows
#define EPSV  1e-4f

typedef unsigned long long ull;

__device__ __forceinline__ ull ffma2(ull a, ull b, ull c) {
    ull d;
    asm("fma.rn.f32x2 %0, %1, %2, %3;" : "=l"(d) : "l"(a), "l"(b), "l"(c));
    return d;
}
__device__ __forceinline__ ull pack2(float lo, float hi) {
    ull d;
    asm("mov.b64 %0, {%1, %2};" : "=l"(d) : "f"(lo), "f"(hi));
    return d;
}
__device__ __forceinline__ float2 unpack2(ull v) {
    float2 r;
    asm("mov.b64 {%0, %1}, %2;" : "=f"(r.x), "=f"(r.y) : "l"(v));
    return r;
}
__device__ __forceinline__ uint32_t smem_u32(const void* p) {
    uint32_t a;
    asm("{ .reg .u64 t; cvta.to.shared.u64 t, %1; cvt.u32.u64 %0, t; }" : "=r"(a) : "l"(p));
    return a;
}

// mma.sync m16n8k16 f16 -> f32 accum
__device__ __forceinline__ void mma_f16(float c[4],
                                        uint32_t a0, uint32_t a1, uint32_t a2, uint32_t a3,
                                        uint32_t b0, uint32_t b1) {
    asm volatile(
        "mma.sync.aligned.m16n8k16.row.col.f32.f16.f16.f32 "
        "{%0,%1,%2,%3}, {%4,%5,%6,%7}, {%8,%9}, {%0,%1,%2,%3};"
        : "+f"(c[0]), "+f"(c[1]), "+f"(c[2]), "+f"(c[3])
        : "r"(a0), "r"(a1), "r"(a2), "r"(a3), "r"(b0), "r"(b1));
}

__device__ __forceinline__ void ldsm_x4(uint32_t& r0, uint32_t& r1, uint32_t& r2, uint32_t& r3,
                                        uint32_t addr) {
    asm volatile("ldmatrix.sync.aligned.m8n8.x4.shared.b16 {%0,%1,%2,%3}, [%4];"
                 : "=r"(r0), "=r"(r1), "=r"(r2), "=r"(r3) : "r"(addr));
}

__device__ __forceinline__ void cp16h(uint32_t daddr, const __half* src, uint32_t bytes) {
    asm volatile("cp.async.ca.shared.global [%0], [%1], 16, %2;"
                 :: "r"(daddr), "l"(src), "r"(bytes));
}
#define CP_COMMIT()  asm volatile("cp.async.commit_group;" ::: "memory")
#define CP_WAIT_1()  asm volatile("cp.async.wait_group 1;" ::: "memory")
#define CP_WAIT_0()  asm volatile("cp.async.wait_group 0;" ::: "memory")

// ---------------- device scratch ----------------
__device__ __align__(128) float  g_gibase[BSZ * GDIM];
__device__ __align__(128) float  g_h0[BSZ * EMB];
__device__ __align__(128) float  g_whh_t[EMB * GDIM];
__device__ __align__(128) float  g_bdc[400];                      // packed dec_b1|cov_b1
__device__ __align__(128) __half g_h1h[(size_t)MBIG * EMB];
__device__ __align__(128) __half g_ctxh[BSZ * EMB];
__device__ __align__(128) __half g_alch[(size_t)MBIG * 400];
__device__ __align__(128) __half g_gih[(size_t)MBIG * GDIM];
__device__ __align__(128) __half g_hidh[(size_t)MROWS * EMB];
__device__ __align__(128) __half g_tmph[(size_t)MROWS * 400];     // fused dec|cov hidden (half)
__device__ __align__(128) __half g_uh[(size_t)MBIG * 8];          // padded half u
__device__ __align__(128) __half g_lch[(size_t)MBIG * 8];         // padded half lctx
__device__ __align__(128) __half g_wh[604000];

#define WH_SE   0
#define WH_CE   40000
#define WH_AE   80000
#define WH_LCE  120000
#define WH_DEC  160000      // dec_w1 rows 0-199 ...
#define WH_COV  200000      // ... cov_w1 rows 200-399 (contiguous => [400][200])
#define WH_WIH  240000      // 600x600
#define WH_AE1  600000      // ae_w1 padded [200][8]
#define WH_LCE1 601600      // lce_w1 padded [200][8]

// ---------------- fp16 tensor-core GEMM (round-11 proven config) ----------------
#define ROWB      144                 // bytes per smem tile row (64 halves + 8 pad)
#define TILE_B    (128 * ROWB)        // 18432
#define BUF_B     (2 * TILE_B)        // 36864
#define HM_SMEM   (2 * BUF_B)         // 73728

enum { ACT_NONE = 0, ACT_RELU = 1, ACT_TANH = 2 };

// stage [128 rows x 64 halves] via cp.async (zero-fills beyond K / rows)
__device__ __forceinline__ void stage_h64(uint32_t sbase, const __half* __restrict__ src,
                                          int ld, int row0, int rowsValid,
                                          int k0, int K, int tid)
{
#pragma unroll
    for (int pass = 0; pass < 4; pass++) {
        int e = tid + pass * 256;
        int r = e >> 3, c = e & 7;
        int ks = k0 + c * 8;
        int valid = (r < rowsValid) ? min(max((K - ks) * 2, 0), 16) : 0;
        const __half* g = src + (size_t)(row0 + ((r < rowsValid) ? r : 0)) * ld + (valid ? ks : 0);
        cp16h(sbase + (uint32_t)(r * ROWB + c * 16), g, (uint32_t)valid);
    }
}

template <int ACT, bool HAS_BASE>
__global__ void __launch_bounds__(256, 2)
hm_gemm(const __half* __restrict__ A, int lda,
        const __half* __restrict__ W, int ldw,
        const float* __restrict__ bias,
        const float* __restrict__ base, int baseMask,
        float* __restrict__ outF, int ldf,
        __half* __restrict__ outH, int ldh,
        int M, int N, int K)
{
    extern __shared__ char smh[];
    const uint32_t smem_base = smem_u32(smh);

    const int tid  = threadIdx.x;
    const int wid  = tid >> 5;
    const int lane = tid & 31;
    const int warp_m = wid >> 1;
    const int warp_n = wid & 1;
    const int bm = blockIdx.y * 128;
    const int bn = blockIdx.x * 128;
    const int nValid = min(128, N - bn);

    const int lg = lane >> 2;
    const int lt = lane & 3;

    const uint32_t aRow = (uint32_t)(warp_m * 32 + (lane & 15));
    const uint32_t aOff = aRow * ROWB + ((lane >> 4) << 3) * 2;
    const uint32_t bRow = (uint32_t)(warp_n * 64 + ((lane >> 4) & 1) * 8 + (lane & 7));
    const uint32_t bOff = bRow * ROWB + (((lane >> 3) & 1) << 3) * 2;

    float acc[2][8][4];
#pragma unroll
    for (int mt = 0; mt < 2; mt++)
#pragma unroll
        for (int nt = 0; nt < 8; nt++)
#pragma unroll
            for (int j = 0; j < 4; j++) acc[mt][nt][j] = 0.f;

    const int nk = (K + 63) / 64;

    stage_h64(smem_base,          A, lda, bm, 128,    0, K, tid);
    stage_h64(smem_base + TILE_B, W, ldw, bn, nValid, 0, K, tid);
    CP_COMMIT();

    for (int kc = 0; kc < nk; kc++) {
        if (kc + 1 < nk) {
            uint32_t nb = smem_base + (uint32_t)(((kc + 1) & 1) * BUF_B);
            int k0n = (kc + 1) * 64;
            stage_h64(nb,          A, lda, bm, 128,    k0n, K, tid);
            stage_h64(nb + TILE_B, W, ldw, bn, nValid, k0n, K, tid);
            CP_COMMIT();
            CP_WAIT_1();
        } else {
            CP_WAIT_0();
        }
        __syncthreads();

        const uint32_t aBase = smem_base + (uint32_t)((kc & 1) * BUF_B) + aOff;
        const uint32_t bBase = smem_base + (uint32_t)((kc & 1) * BUF_B) + TILE_B + bOff;

        const int kRem = K - kc * 64;
        const int kkmax = min(4, (kRem + 15) >> 4);

#pragma unroll 4
        for (int kk = 0; kk < kkmax; kk++) {
            const uint32_t kByte = (uint32_t)(kk * 32);
            uint32_t af[2][4];
            ldsm_x4(af[0][0], af[0][1], af[0][2], af[0][3], aBase + kByte);
            ldsm_x4(af[1][0], af[1][1], af[1][2], af[1][3], aBase + 16 * ROWB + kByte);
#pragma unroll
            for (int p = 0; p < 4; p++) {
                uint32_t b00, b01, b10, b11;
                ldsm_x4(b00, b01, b10, b11, bBase + (uint32_t)(p * 16 * ROWB) + kByte);
                mma_f16(acc[0][2 * p],     af[0][0], af[0][1], af[0][2], af[0][3], b00, b01);
                mma_f16(acc[1][2 * p],     af[1][0], af[1][1], af[1][2], af[1][3], b00, b01);
                mma_f16(acc[0][2 * p + 1], af[0][0], af[0][1], af[0][2], af[0][3], b10, b11);
                mma_f16(acc[1][2 * p + 1], af[1][0], af[1][1], af[1][2], af[1][3], b10, b11);
            }
        }
        __syncthreads();
    }

#pragma unroll
    for (int mt = 0; mt < 2; mt++) {
        int gm0 = bm + warp_m * 32 + mt * 16 + lg;
        const float* base0 = HAS_BASE ? (base + (size_t)(gm0 & baseMask) * GDIM) : nullptr;
        const float* base1 = HAS_BASE ? (base + (size_t)((gm0 + 8) & baseMask) * GDIM) : nullptr;
#pragma unroll
        for (int nt = 0; nt < 8; nt++) {
            int gnl = warp_n * 64 + nt * 8 + lt * 2;
            if (gnl >= nValid) continue;
            int gn = bn + gnl;
            float b0v = bias ? bias[gn]     : 0.f;
            float b1v = bias ? bias[gn + 1] : 0.f;
            float v00 = acc[mt][nt][0] + b0v;
            float v01 = acc[mt][nt][1] + b1v;
            float v10 = acc[mt][nt][2] + b0v;
            float v11 = acc[mt][nt][3] + b1v;
            if (HAS_BASE) {
                v00 += base0[gn]; v01 += base0[gn + 1];
                v10 += base1[gn]; v11 += base1[gn + 1];
            }
            if (ACT == ACT_RELU) {
                v00 = fmaxf(v00, 0.f); v01 = fmaxf(v01, 0.f);
                v10 = fmaxf(v10, 0.f); v11 = fmaxf(v11, 0.f);
            } else if (ACT == ACT_TANH) {
                v00 = tanhf(v00); v01 = tanhf(v01);
                v10 = tanhf(v10); v11 = tanhf(v11);
            }
            if (outF) {
                *reinterpret_cast<float2*>(outF + (size_t)gm0 * ldf + gn)       = make_float2(v00, v01);
                *reinterpret_cast<float2*>(outF + (size_t)(gm0 + 8) * ldf + gn) = make_float2(v10, v11);
            }
            if (outH) {
                *reinterpret_cast<__half2*>(outH + (size_t)gm0 * ldh + gn)       = __floats2half2_rn(v00, v01);
                *reinterpret_cast<__half2*>(outH + (size_t)(gm0 + 8) * ldh + gn) = __floats2half2_rn(v10, v11);
            }
        }
    }
}

// ---------------- tiny-K first layer (half output; small M only) ----------------
__global__ void embed1_kernel(const float* __restrict__ X,
                              const float* __restrict__ W,
                              const float* __restrict__ B,
                              __half* __restrict__ Y, int M, int K)
{
    int idx = blockIdx.x * blockDim.x + threadIdx.x;
    if (idx >= M * EMB) return;
    int m = idx / EMB, j = idx - m * EMB;
    const float* xr = X + (size_t)m * K;
    const float* wr = W + (size_t)j * K;
    float s = B[j];
    for (int k = 0; k < K; k++) s = fmaf(xr[k], wr[k], s);
    Y[idx] = __float2half(fmaxf(s, 0.f));
}

// ---------------- convert weights to half (+ padded layer-1 weights, dec|cov bias) ----------------
__global__ void conv_w_kernel(const float* __restrict__ se, const float* __restrict__ ce,
                              const float* __restrict__ ae, const float* __restrict__ lce,
                              const float* __restrict__ dec, const float* __restrict__ cov,
                              const float* __restrict__ wih, __half* __restrict__ wh,
                              const float* __restrict__ decb, const float* __restrict__ covb,
                              float* __restrict__ bdc,
                              const float* __restrict__ aew1, const float* __restrict__ lcew1)
{
    int i = blockIdx.x * blockDim.x + threadIdx.x;
    if (i < 40000) {
        wh[WH_SE  + i] = __float2half(se[i]);
        wh[WH_CE  + i] = __float2half(ce[i]);
        wh[WH_AE  + i] = __float2half(ae[i]);
        wh[WH_LCE + i] = __float2half(lce[i]);
        wh[WH_DEC + i] = __float2half(dec[i]);
        wh[WH_COV + i] = __float2half(cov[i]);
    }
    if (i < 360000) wh[WH_WIH + i] = __float2half(wih[i]);
    if (i < 200) {
        bdc[i]       = decb[i];
        bdc[200 + i] = covb[i];
    }
    if (i < 1600) {
        int r = i >> 3, c = i & 7;
        wh[WH_AE1  + i] = (c < 4) ? __float2half(aew1[r * 4 + c])  : __float2half(0.f);
        wh[WH_LCE1 + i] = (c < 6) ? __float2half(lcew1[r * 6 + c]) : __float2half(0.f);
    }
}

// ---------------- pad+convert u / lctx to half [MBIG x 8] ----------------
__global__ void conv_in_kernel(const float* __restrict__ u,
                               const float* __restrict__ lctx,
                               __half* __restrict__ uh,
                               __half* __restrict__ lch)
{
    int i = blockIdx.x * blockDim.x + threadIdx.x;
    if (i >= MBIG * 8) return;
    int r = i >> 3, c = i & 7;
    uh[i]  = (c < 4) ? __float2half(u[r * 4 + c])    : __float2half(0.f);
    lch[i] = (c < 6) ? __float2half(lctx[r * 6 + c]) : __float2half(0.f);
}

// ---------------- Whh transpose ----------------
__global__ void transpose_whh_kernel(const float* __restrict__ W,
                                     float* __restrict__ Wt)
{
    int idx = blockIdx.x * blockDim.x + threadIdx.x;
    if (idx >= GDIM * EMB) return;
    int c = idx / EMB, k = idx - c * EMB;
    Wt[k * GDIM + c] = W[idx];
}

// ---------------- persistent fused GRU scan: 256 CTAs x 8 rows, gi cp.async prefetch ----------------
#define SCAN_CTAS    256
#define ROWS_PER     8
#define SCAN_THREADS 320
#define H2S_BYTES    (200 * 5 * 8)      // 8000: [200][4 pairs + 1 pad] ull
#define GHS_BYTES    (600 * 10 * 4)     // 24000: [600][8 + 2 pad] float
#define BHH_BYTES    (600 * 4)          // 2400
#define GI_BYTES     (ROWS_PER * GDIM * 2)   // 9600 per buffer
#define GI_OFF       (H2S_BYTES + GHS_BYTES + BHH_BYTES)     // 34400
#define SCAN_SMEM    (GI_OFF + 2 * GI_BYTES)                 // 53600

__global__ void __launch_bounds__(SCAN_THREADS, 2)
scan_kernel(const float* __restrict__ Wt,
            const float* __restrict__ bhh,
            const __half* __restrict__ gih,
            const float* __restrict__ h0,
            __half* __restrict__ hidh)
{
    extern __shared__ char sm[];
    ull   (*h2s)[5]  = reinterpret_cast<ull(*)[5]>(sm);
    float (*ghs)[10] = reinterpret_cast<float(*)[10]>(sm + H2S_BYTES);
    float* bhh_s     = reinterpret_cast<float*>(sm + H2S_BYTES + GHS_BYTES);
    float* hsf       = reinterpret_cast<float*>(sm);    // float view, row stride 10
    const uint32_t smem_base = smem_u32(sm);
    const uint32_t gi_smem0  = smem_base + GI_OFF;

    const int tid = threadIdx.x;
    const int b0  = blockIdx.x * ROWS_PER;
    const float2* Wt2 = reinterpret_cast<const float2*>(Wt);

    for (int j = tid; j < GDIM; j += SCAN_THREADS) bhh_s[j] = bhh[j];
    for (int e = tid; e < ROWS_PER * EMB; e += SCAN_THREADS) {
        int r = e / EMB, j = e - r * EMB;
        hsf[j * 10 + r] = h0[(size_t)(b0 + r) * EMB + j];
    }

    // prefetch gi[t=0] into buffer 0 (4800 halves = 600 x 16B, contiguous)
    {
        const __half* g0 = gih + (size_t)b0 * GDIM;   // t=0
#pragma unroll
        for (int p = 0; p < 2; p++) {
            int s = tid + p * SCAN_THREADS;           // 0..639
            if (s < 600) cp16h(gi_smem0 + (uint32_t)(s * 16), g0 + s * 8, 16);
        }
        CP_COMMIT();
    }
    __syncthreads();

    const bool active = (tid < 300);

    for (int t = 0; t < TST; t++) {
        // prefetch gi[t+1] into the other buffer (its old content was consumed at t-1)
        if (t + 1 < TST) {
            const __half* gn = gih + ((size_t)(t + 1) * BSZ + b0) * GDIM;
            uint32_t dst = gi_smem0 + (uint32_t)(((t + 1) & 1) * GI_BYTES);
#pragma unroll
            for (int p = 0; p < 2; p++) {
                int s = tid + p * SCAN_THREADS;
                if (s < 600) cp16h(dst + (uint32_t)(s * 16), gn + s * 8, 16);
            }
            CP_COMMIT();
        }

        // ---- gh = h @ Whh^T : thread owns cols (2t,2t+1), 4 row-pairs ----
        if (active) {
            ull acc0[4], acc1[4];
#pragma unroll
            for (int p = 0; p < 4; p++) { acc0[p] = 0ull; acc1[p] = 0ull; }

            float2 wbuf[4];
#pragma unroll
            for (int i = 0; i < 4; i++) wbuf[i] = Wt2[i * 300 + tid];

#pragma unroll 4
            for (int k = 0; k < EMB; k++) {
                float2 w = wbuf[k & 3];
                if (k + 4 < EMB) wbuf[k & 3] = Wt2[(k + 4) * 300 + tid];
                ull w0 = pack2(w.x, w.x);
                ull w1 = pack2(w.y, w.y);
                ull h0v = h2s[k][0], h1v = h2s[k][1], h2v = h2s[k][2], h3v = h2s[k][3];
                acc0[0] = ffma2(h0v, w0, acc0[0]);  acc1[0] = ffma2(h0v, w1, acc1[0]);
                acc0[1] = ffma2(h1v, w0, acc0[1]);  acc1[1] = ffma2(h1v, w1, acc1[1]);
                acc0[2] = ffma2(h2v, w0, acc0[2]);  acc1[2] = ffma2(h2v, w1, acc1[2]);
                acc0[3] = ffma2(h3v, w0, acc0[3]);  acc1[3] = ffma2(h3v, w1, acc1[3]);
            }

            int c0 = 2 * tid, c1 = 2 * tid + 1;
            float2* g0 = reinterpret_cast<float2*>(&ghs[c0][0]);
            float2* g1 = reinterpret_cast<float2*>(&ghs[c1][0]);
#pragma unroll
            for (int p = 0; p < 4; p++) {
                g0[p] = unpack2(acc0[p]);
                g1[p] = unpack2(acc1[p]);
            }
        }
        // gi[t] must have landed (the only possibly-pending group is t+1's)
        if (t + 1 < TST) { CP_WAIT_1(); } else { CP_WAIT_0(); }
        __syncthreads();

        // ---- gate combine + in-place h update + global (half) store ----
        {
            const __half* sgi = reinterpret_cast<const __half*>(sm + GI_OFF + (t & 1) * GI_BYTES);
            __half* hout = hidh + ((size_t)(t + 1) * BSZ + b0) * EMB;
#pragma unroll
            for (int it = 0; it < (ROWS_PER * EMB) / SCAN_THREADS; it++) {
                int e = tid + it * SCAN_THREADS;
                int r = e / EMB, j = e - r * EMB;
                const __half* gr = sgi + r * GDIM;
                float gir = __half2float(gr[j]);
                float giz = __half2float(gr[j + 200]);
                float gin = __half2float(gr[j + 400]);
                float ghr = ghs[j][r]       + bhh_s[j];
                float ghz = ghs[j + 200][r] + bhh_s[j + 200];
                float ghn = ghs[j + 400][r] + bhh_s[j + 400];
                float rg = 1.f / (1.f + expf(-(gir + ghr)));
                float z  = 1.f / (1.f + expf(-(giz + ghz)));
                float n  = tanhf(gin + rg * ghn);
                float hold = hsf[j * 10 + r];
                float hnew = (1.f - z) * n + z * hold;
                hsf[j * 10 + r] = hnew;
                hout[(size_t)r * EMB + j] = __float2half(hnew);
            }
        }
        __syncthreads();
    }
}

// ---------------- fused 400 -> (12 mean, 12 std) projection (half input) ----------------
__global__ void proj2_kernel(const __half* __restrict__ T,
                             const float* __restrict__ decw2,
                             const float* __restrict__ decb2,
                             const float* __restrict__ covw2,
                             const float* __restrict__ covb2,
                             float* __restrict__ outM,
                             float* __restrict__ outS, int M)
{
    int warp = (blockIdx.x * blockDim.x + threadIdx.x) >> 5;
    int lane = threadIdx.x & 31;
    if (warp >= M) return;
    const __half* row = T + (size_t)warp * 400;
    float am[SDIM], as[SDIM];
#pragma unroll
    for (int s = 0; s < SDIM; s++) { am[s] = 0.f; as[s] = 0.f; }
    for (int k = lane; k < EMB; k += 32) {
        float t0 = __half2float(row[k]);
        float t1 = __half2float(row[200 + k]);
#pragma unroll
        for (int s = 0; s < SDIM; s++) {
            am[s] = fmaf(t0, decw2[s * EMB + k], am[s]);
            as[s] = fmaf(t1, covw2[s * EMB + k], as[s]);
        }
    }
#pragma unroll
    for (int s = 0; s < SDIM; s++) {
#pragma unroll
        for (int off = 16; off > 0; off >>= 1) {
            am[s] += __shfl_xor_sync(0xffffffffu, am[s], off);
            as[s] += __shfl_xor_sync(0xffffffffu, as[s], off);
        }
    }
    if (lane == 0) {
        float* om = outM + (size_t)warp * SDIM;
        float* os = outS + (size_t)warp * SDIM;
#pragma unroll
        for (int s = 0; s < SDIM; s++) {
            om[s] = am[s] + decb2[s];
            float v = as[s] + covb2[s];
            float sp = log1pf(expf(-fabsf(v))) + fmaxf(v, 0.f);
            os[s] = sqrtf(sp + EPSV);
        }
    }
}

// ---------------- host-side ----------------
static void launch_hm(int act, const __half* A, int lda, const __half* W, int ldw,
                      const float* bias, const float* base, int baseMask,
                      float* outF, int ldf, __half* outH, int ldh,
                      int M, int N, int K)
{
    dim3 grid((N + 127) / 128, M / 128);
    dim3 blk(256);
    size_t shm = HM_SMEM;
    if (base) {
        if (act == ACT_NONE)      hm_gemm<ACT_NONE, true><<<grid, blk, shm>>>(A, lda, W, ldw, bias, base, baseMask, outF, ldf, outH, ldh, M, N, K);
        else if (act == ACT_RELU) hm_gemm<ACT_RELU, true><<<grid, blk, shm>>>(A, lda, W, ldw, bias, base, baseMask, outF, ldf, outH, ldh, M, N, K);
        else                      hm_gemm<ACT_TANH, true><<<grid, blk, shm>>>(A, lda, W, ldw, bias, base, baseMask, outF, ldf, outH, ldh, M, N, K);
    } else {
        if (act == ACT_NONE)      hm_gemm<ACT_NONE, false><<<grid, blk, shm>>>(A, lda, W, ldw, bias, nullptr, 0, outF, ldf, outH, ldh, M, N, K);
        else if (act == ACT_RELU) hm_gemm<ACT_RELU, false><<<grid, blk, shm>>>(A, lda, W, ldw, bias, nullptr, 0, outF, ldf, outH, ldh, M, N, K);
        else                      hm_gemm<ACT_TANH, false><<<grid, blk, shm>>>(A, lda, W, ldw, bias, nullptr, 0, outF, ldf, outH, ldh, M, N, K);
    }
}

extern "C" void kernel_launch(void* const* d_in, const int* in_sizes, int n_in,
                              void* d_out, int out_size)
{
    const float* x        = (const float*)d_in[0];
    const float* u        = (const float*)d_in[1];
    const float* ctx_mean = (const float*)d_in[2];
    const float* lctx     = (const float*)d_in[3];
    const float* se_w1 = (const float*)d_in[4];  const float* se_b1 = (const float*)d_in[5];
    const float* se_w2 = (const float*)d_in[6];  const float* se_b2 = (const float*)d_in[7];
    const float* ae_w1 = (const float*)d_in[8];  const float* ae_b1 = (const float*)d_in[9];
    const float* ae_w2 = (const float*)d_in[10]; const float* ae_b2 = (const float*)d_in[11];
    const float* ce_w1 = (const float*)d_in[12]; const float* ce_b1 = (const float*)d_in[13];
    const float* ce_w2 = (const float*)d_in[14]; const float* ce_b2 = (const float*)d_in[15];
    const float* lce_w1 = (const float*)d_in[16]; const float* lce_b1 = (const float*)d_in[17];
    const float* lce_w2 = (const float*)d_in[18]; const float* lce_b2 = (const float*)d_in[19];
    const float* dec_w1 = (const float*)d_in[20]; const float* dec_b1 = (const float*)d_in[21];
    const float* dec_w2 = (const float*)d_in[22]; const float* dec_b2 = (const float*)d_in[23];
    const float* gru_wih = (const float*)d_in[24]; const float* gru_bih = (const float*)d_in[25];
    const float* gru_whh = (const float*)d_in[26]; const float* gru_bhh = (const float*)d_in[27];
    const float* cov_w1 = (const float*)d_in[28]; const float* cov_b1 = (const float*)d_in[29];
    const float* cov_w2 = (const float*)d_in[30]; const float* cov_b2 = (const float*)d_in[31];

    float  *p_gibase, *p_h0, *p_wt, *p_bdc;
    __half *p_h1h, *p_ctxh, *p_alch, *p_gih, *p_hidh, *p_tmph, *p_uh, *p_lch, *p_wh;
    cudaGetSymbolAddress((void**)&p_gibase, g_gibase);
    cudaGetSymbolAddress((void**)&p_h0,     g_h0);
    cudaGetSymbolAddress((void**)&p_wt,     g_whh_t);
    cudaGetSymbolAddress((void**)&p_bdc,    g_bdc);
    cudaGetSymbolAddress((void**)&p_h1h,    g_h1h);
    cudaGetSymbolAddress((void**)&p_ctxh,   g_ctxh);
    cudaGetSymbolAddress((void**)&p_alch,   g_alch);
    cudaGetSymbolAddress((void**)&p_gih,    g_gih);
    cudaGetSymbolAddress((void**)&p_hidh,   g_hidh);
    cudaGetSymbolAddress((void**)&p_tmph,   g_tmph);
    cudaGetSymbolAddress((void**)&p_uh,     g_uh);
    cudaGetSymbolAddress((void**)&p_lch,    g_lch);
    cudaGetSymbolAddress((void**)&p_wh,     g_wh);

    cudaFuncSetAttribute(scan_kernel, cudaFuncAttributeMaxDynamicSharedMemorySize, SCAN_SMEM);
    cudaFuncSetAttribute(hm_gemm<ACT_NONE, true>,  cudaFuncAttributeMaxDynamicSharedMemorySize, HM_SMEM);
    cudaFuncSetAttribute(hm_gemm<ACT_RELU, true>,  cudaFuncAttributeMaxDynamicSharedMemorySize, HM_SMEM);
    cudaFuncSetAttribute(hm_gemm<ACT_TANH, true>,  cudaFuncAttributeMaxDynamicSharedMemorySize, HM_SMEM);
    cudaFuncSetAttribute(hm_gemm<ACT_NONE, false>, cudaFuncAttributeMaxDynamicSharedMemorySize, HM_SMEM);
    cudaFuncSetAttribute(hm_gemm<ACT_RELU, false>, cudaFuncAttributeMaxDynamicSharedMemorySize, HM_SMEM);
    cudaFuncSetAttribute(hm_gemm<ACT_TANH, false>, cudaFuncAttributeMaxDynamicSharedMemorySize, HM_SMEM);

    float* out_mean = (float*)d_out;
    float* out_std  = out_mean + (size_t)MROWS * SDIM;

    const int eb = 256;

    conv_w_kernel<<<(360000 + eb - 1) / eb, eb>>>(se_w2, ce_w2, ae_w2, lce_w2,
                                                  dec_w1, cov_w1, gru_wih, p_wh,
                                                  dec_b1, cov_b1, p_bdc,
                                                  ae_w1, lce_w1);
    conv_in_kernel<<<(MBIG * 8 + eb - 1) / eb, eb>>>(u, lctx, p_uh, p_lch);
    transpose_whh_kernel<<<(GDIM * EMB + eb - 1) / eb, eb>>>(gru_whh, p_wt);

    // state_embed -> h0 (fp32 for scan) + hidh block 0 (half for dec/cov)
    embed1_kernel<<<(BSZ * EMB + eb - 1) / eb, eb>>>(x, se_w1, se_b1, p_h1h, BSZ, SDIM);
    launch_hm(ACT_TANH, p_h1h, EMB, p_wh + WH_SE, EMB, se_b2, nullptr, 0,
              p_h0, EMB, p_hidh, EMB, BSZ, EMB, EMB);

    // ctx_embed (half), then gi_base (fp32)
    embed1_kernel<<<(BSZ * EMB + eb - 1) / eb, eb>>>(ctx_mean, ce_w1, ce_b1, p_h1h, BSZ, 8);
    launch_hm(ACT_RELU, p_h1h, EMB, p_wh + WH_CE, EMB, ce_b2, nullptr, 0,
              nullptr, 0, p_ctxh, EMB, BSZ, EMB, EMB);
    launch_hm(ACT_NONE, p_ctxh, EMB, p_wh + WH_WIH, GDIM, gru_bih, nullptr, 0,
              p_gibase, GDIM, nullptr, 0, BSZ, GDIM, EMB);

    // action embed layer1 (tensor-core, K=8) -> h1h, then layer2 -> alc[:, 0:200]
    launch_hm(ACT_RELU, p_uh, 8, p_wh + WH_AE1, 8, ae_b1, nullptr, 0,
              nullptr, 0, p_h1h, EMB, MBIG, EMB, 8);
    launch_hm(ACT_RELU, p_h1h, EMB, p_wh + WH_AE, EMB, ae_b2, nullptr, 0,
              nullptr, 0, p_alch, 400, MBIG, EMB, EMB);

    // local ctx embed layer1 (tensor-core, K=8) -> h1h, then layer2 -> alc[:, 200:400]
    launch_hm(ACT_RELU, p_lch, 8, p_wh + WH_LCE1, 8, lce_b1, nullptr, 0,
              nullptr, 0, p_h1h, EMB, MBIG, EMB, 8);
    launch_hm(ACT_RELU, p_h1h, EMB, p_wh + WH_LCE, EMB, lce_b2, nullptr, 0,
              nullptr, 0, p_alch + 200, 400, MBIG, EMB, EMB);

    // gi = [a|lc] @ Wih[:,200:600]^T + gi_base  (half out)
    launch_hm(ACT_NONE, p_alch, 400, p_wh + WH_WIH + 200, GDIM, nullptr, p_gibase, BSZ - 1,
              nullptr, 0, p_gih, GDIM, MBIG, GDIM, 400);

    // fused persistent GRU scan (256 CTAs, 2/SM, gi prefetch)
    scan_kernel<<<SCAN_CTAS, SCAN_THREADS, SCAN_SMEM>>>(p_wt, gru_bhh, p_gih, p_h0, p_hidh);

    // fused dec|cov hidden layer: tmph[M][400] (half)
    launch_hm(ACT_RELU, p_hidh, EMB, p_wh + WH_DEC, EMB, p_bdc, nullptr, 0,
              nullptr, 0, p_tmph, 400, MROWS, 400, EMB);

    // fused projection: mean + std
    {
        int blocks = (MROWS * 32 + 255) / 256;
        proj2_kernel<<<blocks, 256>>>(p_tmph, dec_w2, dec_b2, cov_w2, cov_b2,
                                      out_mean, out_std, MROWS);
    }

    (void)in_sizes; (void)n_in; (void)out_size;
}